// round 8
// baseline (speedup 1.0000x reference)
#include <cuda_runtime.h>
#include <cstdint>

// ---------------------------------------------------------------------------
// FocalLoss (RetinaNet), two lean kernels.
// B=8, A=65536, C=80, M=32. ALPHA=0.5 => stream computes only the negative
// formula  NEG_W * v^2 * max(lg2(1-v), lg2(1e-4)),  NEG_W = -0.5*ln2, with a
// per-anchor weight w in {0 (ignore), NEG_W (valid)}; positives get a scalar
// fix-up for their true class inside the ASSIGN kernel.
//
// assign_kernel (issue-bound, no big streams): division-free IoU argmax with
// the cancellation  iou_m > iou_b  <=>  inter_m*S_b > inter_b*S_m  where
// S = area_a + area_m  (so union never computed in-loop; thresholds become
// 3*inter >= S (iou>=0.5) and 3.5*inter >= S (iou>=0.4), applied post-loop).
// Writes w to g_w[B*A], accumulates reg loss / fix-ups / pos count.
//
// cls_stream_kernel (pure DRAM-bound): stages 512 weights to smem, streams
// classifications as ulonglong2 with packed f32x2 math, block-reduces, and
// the last block finalizes out[2] and resets accumulators for graph replay.
// ---------------------------------------------------------------------------

#define MAX_B   8
#define MAX_M   64
#define MAX_BA  (8 * 65536)
#define ABLK    512
#define ATHR    256
#define NTHR    320
#define NWARP   (NTHR / 32)
#define AWARP   (ATHR / 32)

__device__ double g_cls_sum[MAX_B];
__device__ double g_reg_sum[MAX_B];
__device__ int    g_pos_cnt[MAX_B];
__device__ int    g_done;
__device__ float  g_w[MAX_BA];

__device__ __forceinline__ float lg2f(float x) {
    float r;
    asm("lg2.approx.f32 %0, %1;" : "=f"(r) : "f"(x));
    return r;
}

typedef unsigned long long ull;

__device__ __forceinline__ ull pack2(float lo, float hi) {
    ull r; asm("mov.b64 %0, {%1, %2};" : "=l"(r) : "f"(lo), "f"(hi)); return r;
}
__device__ __forceinline__ void unpack2(ull v, float& lo, float& hi) {
    asm("mov.b64 {%0, %1}, %2;" : "=f"(lo), "=f"(hi) : "l"(v));
}
__device__ __forceinline__ ull fma2(ull a, ull b, ull c) {
    ull r; asm("fma.rn.f32x2 %0, %1, %2, %3;" : "=l"(r) : "l"(a), "l"(b), "l"(c)); return r;
}
__device__ __forceinline__ ull mul2(ull a, ull b) {
    ull r; asm("mul.rn.f32x2 %0, %1, %2;" : "=l"(r) : "l"(a), "l"(b)); return r;
}

#define LCL   (-13.28771237954945f)        /* lg2(1e-4) */
#define NEG_W (-0.34657359027997264f)      /* -0.5*ln(2) */

// acc += wgt2 * v^2 * max(lg2(1-v), LCL) for 4 elements (packed pairs)
__device__ __forceinline__ void neg4_acc(ull w01, ull w23, ull wgt2,
                                         ull& acc0, ull& acc1,
                                         ull NEG1, ull ONE2) {
    ull q01 = fma2(w01, NEG1, ONE2);     // 1 - v
    ull q23 = fma2(w23, NEG1, ONE2);
    float q0, q1, q2, q3;
    unpack2(q01, q0, q1); unpack2(q23, q2, q3);
    float l0 = fmaxf(lg2f(q0), LCL), l1 = fmaxf(lg2f(q1), LCL);
    float l2 = fmaxf(lg2f(q2), LCL), l3 = fmaxf(lg2f(q3), LCL);
    ull L01 = pack2(l0, l1), L23 = pack2(l2, l3);
    ull t01 = mul2(w01, w01), t23 = mul2(w23, w23);
    acc0 = fma2(mul2(t01, L01), wgt2, acc0);
    acc1 = fma2(mul2(t23, L23), wgt2, acc1);
}

// ---------------------------------------------------------------------------
// Kernel 1: assignment (issue-bound). grid (A/ABLK, B), ATHR threads.
// ---------------------------------------------------------------------------
__global__ void __launch_bounds__(ATHR)
assign_kernel(const float* __restrict__ anchors,      // [A,4]
              const float* __restrict__ regressions,  // [B,A,4]
              const float* __restrict__ annotations,  // [B,M,5]
              const float* __restrict__ cls,          // [B,A,C]
              int A, int C, int M)
{
    const int b    = blockIdx.y;
    const int a0   = blockIdx.x * ABLK;
    const int tid  = threadIdx.x;
    const int nA   = min(a0 + ABLK, A) - a0;

    __shared__ float4 s_box[MAX_M];
    __shared__ float  s_area[MAX_M];
    __shared__ float  s_lab[MAX_M];
    __shared__ float  sw_c[AWARP], sw_r[AWARP];
    __shared__ int    sw_i[AWARP];

    if (tid < M) {
        const float* an = annotations + (size_t)b * M * 5 + tid * 5;
        float x1 = an[0], y1 = an[1], x2 = an[2], y2 = an[3];
        s_box[tid]  = make_float4(x1, y1, x2, y2);
        s_area[tid] = (x2 - x1) * (y2 - y1);
        s_lab[tid]  = an[4];
    }
    __syncthreads();

    float regsum = 0.0f;
    float fixsum = 0.0f;
    int   poscnt = 0;

    for (int la = tid; la < nA; la += ATHR) {
        const int a = a0 + la;
        float4 an = reinterpret_cast<const float4*>(anchors)[a];
        float aw = an.z - an.x;
        float ah = an.w - an.y;
        float area_a = aw * ah;

        // Track (best inter, best S=area_a+area_m, best index).
        // iou_m > iou_best  <=>  inter_m * S_best > inter_best * S_m
        // (exact cancellation of the -inter*inter cross terms).
        float bin, bS;
        int   bi = 0;
        {
            float4 bx = s_box[0];
            float iw = fmaxf(fminf(an.z, bx.z) - fmaxf(an.x, bx.x), 0.0f);
            float ih = fmaxf(fminf(an.w, bx.w) - fmaxf(an.y, bx.y), 0.0f);
            bin = iw * ih;
            bS  = area_a + s_area[0];
        }
        #pragma unroll 8
        for (int m = 1; m < M; m++) {
            float4 bx = s_box[m];
            float iw = fmaxf(fminf(an.z, bx.z) - fmaxf(an.x, bx.x), 0.0f);
            float ih = fmaxf(fminf(an.w, bx.w) - fmaxf(an.y, bx.y), 0.0f);
            float inter = iw * ih;
            float S     = area_a + s_area[m];
            if (inter * bS > bin * S) { bi = m; bin = inter; bS = S; }
        }

        // thresholds: iou = bin/(bS-bin):  >=0.5 <=> 3*bin>=bS ; >=0.4 <=> 3.5*bin>=bS
        bool pos = (3.0f * bin >= bS);
        bool ign = (!pos) && (3.5f * bin >= bS);
        g_w[(size_t)b * A + a] = ign ? 0.0f : NEG_W;

        if (pos) {
            poscnt++;
            float4 gb = s_box[bi];
            float gw = gb.z - gb.x, gh = gb.w - gb.y;
            float gcx = gb.x + 0.5f * gw, gcy = gb.y + 0.5f * gh;  // unclamped
            gw = fmaxf(gw, 1.0f);
            gh = fmaxf(gh, 1.0f);
            float acx = an.x + 0.5f * aw, acy = an.y + 0.5f * ah;
            float t0 = __fdividef(gcx - acx, aw) * 10.0f;
            float t1 = __fdividef(gcy - acy, ah) * 10.0f;
            float t2 = __logf(__fdividef(gw, aw)) * 5.0f;
            float t3 = __logf(__fdividef(gh, ah)) * 5.0f;

            float4 rg = reinterpret_cast<const float4*>(regressions)[(size_t)b * A + a];
            const float th = 1.0f / 9.0f;
            const float c2 = 0.5f / 9.0f;
            float d;
            d = fabsf(t0 - rg.x); regsum += (d <= th) ? 4.5f * d * d : d - c2;
            d = fabsf(t1 - rg.y); regsum += (d <= th) ? 4.5f * d * d : d - c2;
            d = fabsf(t2 - rg.z); regsum += (d <= th) ? 4.5f * d * d : d - c2;
            d = fabsf(t3 - rg.w); regsum += (d <= th) ? 4.5f * d * d : d - c2;

            // classification fix-up for the true class
            int label = (int)s_lab[bi];
            float v  = cls[((size_t)b * A + a) * C + label];
            // subtract exactly what the stream will add
            fixsum -= NEG_W * (v * v * fmaxf(lg2f(1.0f - v), LCL));
            // add the positive-branch term with full clamps
            float pp = fminf(fmaxf(v, 1e-4f), 1.0f - 1e-4f);
            float qq = 1.0f - pp;
            fixsum += 0.5f * qq * qq * (-__logf(pp));
        }
    }

    // block reduce
    #pragma unroll
    for (int off = 16; off > 0; off >>= 1) {
        fixsum += __shfl_down_sync(0xFFFFFFFFu, fixsum, off);
        regsum += __shfl_down_sync(0xFFFFFFFFu, regsum, off);
        poscnt += __shfl_down_sync(0xFFFFFFFFu, poscnt, off);
    }
    int lane = tid & 31, warp = tid >> 5;
    if (lane == 0) { sw_c[warp] = fixsum; sw_r[warp] = regsum; sw_i[warp] = poscnt; }
    __syncthreads();
    if (warp == 0) {
        float cs = (lane < AWARP) ? sw_c[lane] : 0.0f;
        float rs = (lane < AWARP) ? sw_r[lane] : 0.0f;
        int   pc = (lane < AWARP) ? sw_i[lane] : 0;
        #pragma unroll
        for (int off = 4; off > 0; off >>= 1) {
            cs += __shfl_down_sync(0xFFFFFFFFu, cs, off);
            rs += __shfl_down_sync(0xFFFFFFFFu, rs, off);
            pc += __shfl_down_sync(0xFFFFFFFFu, pc, off);
        }
        if (lane == 0) {
            if (cs != 0.0f) atomicAdd(&g_cls_sum[b], (double)cs);
            if (rs != 0.0f) atomicAdd(&g_reg_sum[b], (double)rs);
            if (pc != 0)    atomicAdd(&g_pos_cnt[b], pc);
        }
    }
}

// ---------------------------------------------------------------------------
// Kernel 2: DRAM-bound classification stream. grid (A/ABLK, B), NTHR threads.
// ---------------------------------------------------------------------------
__global__ void __launch_bounds__(NTHR)
cls_stream_kernel(const float* __restrict__ cls,      // [B,A,C]
                  float* __restrict__ out,
                  int A, int C, int B, int total_blocks)
{
    const int b   = blockIdx.y;
    const int a0  = blockIdx.x * ABLK;
    const int tid = threadIdx.x;
    const int nA  = min(a0 + ABLK, A) - a0;

    __shared__ float s_w[ABLK];
    __shared__ float sw_c[NWARP];
    __shared__ int   s_last;

    for (int i = tid; i < nA; i += NTHR)
        s_w[i] = g_w[(size_t)b * A + a0 + i];
    __syncthreads();

    float clssum = 0.0f;
    const ull NEG1 = pack2(-1.0f, -1.0f);
    const ull ONE2 = pack2(1.0f, 1.0f);

    if (C == 80 && nA == ABLK) {
        // 512 anchors * 20 float4 = 10240; 320 threads -> 32 steps, 4 in flight
        const ulonglong2* base = reinterpret_cast<const ulonglong2*>(
            cls + ((size_t)b * A + a0) * 80);
        ull acc0 = pack2(0.0f, 0.0f), acc1 = pack2(0.0f, 0.0f);
        ull acc2 = pack2(0.0f, 0.0f), acc3 = pack2(0.0f, 0.0f);
        int idx = tid;
        int la  = tid / 20;
        #pragma unroll
        for (int k = 0; k < 8; k++) {
            ulonglong2 v0 = base[idx];
            ulonglong2 v1 = base[idx + NTHR];
            ulonglong2 v2 = base[idx + 2 * NTHR];
            ulonglong2 v3 = base[idx + 3 * NTHR];
            float w0 = s_w[la], w1 = s_w[la + 16];
            float w2 = s_w[la + 32], w3 = s_w[la + 48];
            neg4_acc(v0.x, v0.y, pack2(w0, w0), acc0, acc1, NEG1, ONE2);
            neg4_acc(v1.x, v1.y, pack2(w1, w1), acc2, acc3, NEG1, ONE2);
            neg4_acc(v2.x, v2.y, pack2(w2, w2), acc0, acc1, NEG1, ONE2);
            neg4_acc(v3.x, v3.y, pack2(w3, w3), acc2, acc3, NEG1, ONE2);
            idx += 4 * NTHR;
            la  += 64;
        }
        float s0, s1, s2, s3, s4, s5, s6, s7;
        unpack2(acc0, s0, s1); unpack2(acc1, s2, s3);
        unpack2(acc2, s4, s5); unpack2(acc3, s6, s7);
        clssum = ((s0 + s1) + (s2 + s3)) + ((s4 + s5) + (s6 + s7));
    } else {
        const ulonglong2* base = reinterpret_cast<const ulonglong2*>(
            cls + ((size_t)b * A + a0) * C);
        const int n4 = (nA * C) >> 2;
        ull acc0 = pack2(0.0f, 0.0f), acc1 = pack2(0.0f, 0.0f);
        for (int idx = tid; idx < n4; idx += NTHR) {
            int aa = (idx << 2) / C;
            float w = s_w[aa];
            ulonglong2 v = base[idx];
            neg4_acc(v.x, v.y, pack2(w, w), acc0, acc1, NEG1, ONE2);
        }
        float s0, s1, s2, s3;
        unpack2(acc0, s0, s1); unpack2(acc1, s2, s3);
        clssum = (s0 + s1) + (s2 + s3);
    }

    // ---- block reduce + ticket ----
    #pragma unroll
    for (int off = 16; off > 0; off >>= 1)
        clssum += __shfl_down_sync(0xFFFFFFFFu, clssum, off);
    int lane = tid & 31, warp = tid >> 5;
    if (lane == 0) sw_c[warp] = clssum;
    __syncthreads();
    if (warp == 0) {
        float cs = (lane < NWARP) ? sw_c[lane] : 0.0f;
        #pragma unroll
        for (int off = 8; off > 0; off >>= 1)
            cs += __shfl_down_sync(0xFFFFFFFFu, cs, off);
        if (lane == 0) {
            atomicAdd(&g_cls_sum[b], (double)cs);
            __threadfence();
            int prev = atomicAdd(&g_done, 1);
            s_last = (prev == total_blocks - 1) ? 1 : 0;
        }
    }
    __syncthreads();

    // ---- last block: finalize + reset for next graph replay ----
    if (s_last) {
        __threadfence();
        if (warp == 0) {
            double cm = 0.0, rm = 0.0;
            if (lane < B) {
                double cv = *((volatile double*)&g_cls_sum[lane]);
                double rv = *((volatile double*)&g_reg_sum[lane]);
                int    pv = *((volatile int*)&g_pos_cnt[lane]);
                double np = (double)pv;
                cm = cv / fmax(np, 1.0);
                rm = (pv > 0) ? rv / fmax(np * 4.0, 1.0) : 0.0;
            }
            #pragma unroll
            for (int off = 16; off > 0; off >>= 1) {
                cm += __shfl_down_sync(0xFFFFFFFFu, cm, off);
                rm += __shfl_down_sync(0xFFFFFFFFu, rm, off);
            }
            if (lane == 0) {
                out[0] = (float)(cm / (double)B);
                out[1] = (float)(rm / (double)B);
                g_done = 0;
            }
            if (lane < B) {
                g_cls_sum[lane] = 0.0;
                g_reg_sum[lane] = 0.0;
                g_pos_cnt[lane] = 0;
            }
        }
    }
}

// ---------------------------------------------------------------------------
extern "C" void kernel_launch(void* const* d_in, const int* in_sizes, int n_in,
                              void* d_out, int out_size)
{
    const float* classifications = (const float*)d_in[0];  // [B,A,C]
    const float* regressions     = (const float*)d_in[1];  // [B,A,4]
    const float* anchors         = (const float*)d_in[2];  // [1,A,4]
    const float* annotations     = (const float*)d_in[3];  // [B,M,5]
    float* out = (float*)d_out;

    const int A = in_sizes[2] / 4;
    const int B = in_sizes[1] / (4 * A);
    const int C = in_sizes[0] / (B * A);
    const int M = in_sizes[3] / (5 * B);

    const int bx = (A + ABLK - 1) / ABLK;
    dim3 grid(bx, B);
    assign_kernel<<<grid, ATHR>>>(anchors, regressions, annotations,
                                  classifications, A, C, M);
    cls_stream_kernel<<<grid, NTHR>>>(classifications, out, A, C, B, bx * B);
    (void)n_in; (void)out_size;
}